// round 16
// baseline (speedup 1.0000x reference)
#include <cuda_runtime.h>
#include <math.h>

#define NMAX 100000
#define EMAX 1600000
#define H 32
#define BN_EPS 1e-5f
#define NBANK 32
#define NBMAX ((NMAX + 255) / 256)

// ---------------- device scratch (zero-initialized at module load; every
// run restores the zero-invariant in its final kernel) ----------------
__device__ int      g_csr[EMAX];
__device__ int      g_rowstart[NMAX];
__device__ int      g_cursor[NMAX];              // must be 0 at entry
__device__ int      g_deg[NMAX];                 // must be 0 at entry
__device__ float    g_dinv[NMAX];
__device__ float    g_sdinv[NMAX];
__device__ __align__(16) float4 g_x4[NMAX];      // (x*dinv, dinv)
__device__ __align__(16) float g_sA[NMAX * H];
__device__ __align__(16) float g_sB[NMAX * H];
__device__ __align__(16) float g_h[NMAX * H];
__device__ float    g_r[NMAX];
__device__ double   g_sumb[NBANK][H], g_sumsqb[NBANK][H];  // zeroed by bnparams
__device__ float    g_Wp[H * H];
__device__ float    g_kvec[H];
__device__ unsigned g_rmax_bits;                 // must be 0 at entry
__device__ double   g_sumexp;                    // must be 0 at entry
__device__ double   g_wsum[H];                   // must be 0 at entry
__device__ int      g_total;                     // must be 0 at entry
__device__ int      g_blockcnt[NBMAX], g_blockoff[NBMAX], g_C;

__device__ __forceinline__ float warp_sum(float v) {
#pragma unroll
    for (int o = 16; o > 0; o >>= 1) v += __shfl_xor_sync(0xffffffffu, v, o);
    return v;
}

// grouped float4 gather: 4 neighbor-groups x 8 lanes
__device__ __forceinline__ float4 csr_gather4(const float* __restrict__ tab,
                                              int self, int start, int deg,
                                              int grp, int sub) {
    float4 r = make_float4(0.f, 0.f, 0.f, 0.f);
    for (int k = 0; k < deg; k += 8) {
        int k0 = k + grp, k1 = k + 4 + grp;
        if (k0 < deg) {
            int i0 = g_csr[start + k0];
            float4 a = ((const float4*)(tab + (size_t)i0 * H))[sub];
            r.x += a.x; r.y += a.y; r.z += a.z; r.w += a.w;
        }
        if (k1 < deg) {
            int i1 = g_csr[start + k1];
            float4 b = ((const float4*)(tab + (size_t)i1 * H))[sub];
            r.x += b.x; r.y += b.y; r.z += b.z; r.w += b.w;
        }
    }
#pragma unroll
    for (int o = 8; o < 32; o <<= 1) {
        r.x += __shfl_xor_sync(0xffffffffu, r.x, o);
        r.y += __shfl_xor_sync(0xffffffffu, r.y, o);
        r.z += __shfl_xor_sync(0xffffffffu, r.z, o);
        r.w += __shfl_xor_sync(0xffffffffu, r.w, o);
    }
    float4 s = ((const float4*)(tab + (size_t)self * H))[sub];
    r.x += s.x; r.y += s.y; r.z += s.z; r.w += s.w;
    return r;
}

// ---------------- kernels ----------------
// deg atomics (deg is 0 at entry by invariant)
__global__ void k_prep(const int* __restrict__ ei, int e, int n) {
    int t = blockIdx.x * blockDim.x + threadIdx.x;
    if (t >= e) return;
    int d = ei[e + t];
    if ((unsigned)d >= (unsigned)n) d = 0;
    atomicAdd(&g_deg[d], 1);
}

// dinv/x4 + rowstart via block-local scan + one atomicAdd (range order
// across blocks is irrelevant for CSR correctness)
__global__ void k_build(const float* __restrict__ x, int n) {
    __shared__ int sh[256];
    __shared__ int base;
    int tid = threadIdx.x;
    int i = blockIdx.x * 256 + tid;
    int dv = (i < n) ? g_deg[i] : 0;
    if (i < n) {
        float di = rsqrtf((float)(dv + 1));
        g_dinv[i] = di;
        g_x4[i] = make_float4(x[(size_t)i * 3 + 0] * di,
                              x[(size_t)i * 3 + 1] * di,
                              x[(size_t)i * 3 + 2] * di, di);
    }
    sh[tid] = dv;
    __syncthreads();
#pragma unroll
    for (int off = 1; off < 256; off <<= 1) {
        int t = (tid >= off) ? sh[tid - off] : 0;
        __syncthreads();
        sh[tid] += t;
        __syncthreads();
    }
    if (tid == 255) base = atomicAdd(&g_total, sh[255]);
    __syncthreads();
    if (i < n) g_rowstart[i] = base + sh[tid] - dv;
}

__global__ void k_bucket(const int* __restrict__ ei, int e, int n) {
    int t = blockIdx.x * blockDim.x + threadIdx.x;
    if (t >= e) return;
    int s = ei[t];
    int d = ei[e + t];
    if ((unsigned)s >= (unsigned)n) s = 0;
    if ((unsigned)d >= (unsigned)n) d = 0;
    int pos = g_rowstart[d] + atomicAdd(&g_cursor[d], 1);
    g_csr[pos] = s;
}

// conv1: rank-3 gather + W1 + bias/relu + banked stats
__global__ void k_conv1(const float* __restrict__ W, const float* __restrict__ bias,
                        int n) {
    __shared__ float Wsh[3 * H];
    __shared__ float sv[8][H], sq[8][H];
    int tid = threadIdx.x;
    for (int t = tid; t < 3 * H; t += 256) Wsh[t] = W[t];
    __syncthreads();
    int c = tid & 31, w = tid >> 5;
    int i = blockIdx.x * 8 + w;
    float v = 0.f;
    if (i < n) {
        int start = g_rowstart[i];
        int deg = g_deg[i];
        float ax = 0.f, ay = 0.f, az = 0.f, aw = 0.f;
        for (int k = c; k < deg; k += 32) {
            float4 t4 = g_x4[g_csr[start + k]];
            ax += t4.x; ay += t4.y; az += t4.z; aw += t4.w;
        }
        ax = warp_sum(ax); ay = warp_sum(ay); az = warp_sum(az); aw = warp_sum(aw);
        float4 self = g_x4[i];
        ax += self.x; ay += self.y; az += self.z; aw += self.w;
        if (c == 0) g_sdinv[i] = aw;
        float di = g_dinv[i];
        float z = ax * Wsh[0 * H + c] + ay * Wsh[1 * H + c] + az * Wsh[2 * H + c];
        v = fmaxf(z * di + bias[c], 0.f);
        g_sA[(size_t)i * H + c] = v * di;
    }
    sv[w][c] = v; sq[w][c] = v * v;
    __syncthreads();
    if (tid < H) {
        float s = 0.f, q = 0.f;
#pragma unroll
        for (int ww = 0; ww < 8; ww++) { s += sv[ww][tid]; q += sq[ww][tid]; }
        int b = blockIdx.x & (NBANK - 1);
        atomicAdd(&g_sumb[b][tid], (double)s);
        atomicAdd(&g_sumsqb[b][tid], (double)q);
    }
}

// BN params folded into next layer's weight (reads banked stats, zeroes them)
__global__ void k_bnparams(const float* __restrict__ W, const float* __restrict__ g,
                           const float* __restrict__ be, double inv_n) {
    __shared__ float sscale[H], sshift[H];
    int k = threadIdx.x, j = threadIdx.y;
    if (j == 0) {
        double s = 0.0, q = 0.0;
        for (int b = 0; b < NBANK; b++) { s += g_sumb[b][k]; q += g_sumsqb[b][k]; }
        double mu = s * inv_n;
        double var = q * inv_n - mu * mu;
        float scale = g[k] * rsqrtf((float)var + BN_EPS);
        sscale[k] = scale;
        sshift[k] = be[k] - (float)mu * scale;
    }
    __syncthreads();
    float wv = W[k * H + j];
    g_Wp[k * H + j] = sscale[k] * wv;
    float t = sshift[k] * wv;
#pragma unroll
    for (int o = 16; o > 0; o >>= 1) t += __shfl_xor_sync(0xffffffffu, t, o);
    if (k == 0) g_kvec[j] = t;
    g_sumb[j][k] = 0.0;
    g_sumsqb[j][k] = 0.0;
}

// conv2: grouped-float4 gather + commuted matmul + bias/relu + banked stats
__global__ void k_conv2(const float* __restrict__ bias, int n) {
    __shared__ float Wsh[H * H];
    __shared__ float kv[H];
    __shared__ float sv[8][H], sq[8][H];
    int tid = threadIdx.x;
    for (int t = tid; t < H * H; t += 256) Wsh[t] = g_Wp[t];
    if (tid < H) kv[tid] = g_kvec[tid];
    __syncthreads();
    int c = tid & 31, w = tid >> 5;
    int grp = c >> 3, sub = c & 7;
    int i = blockIdx.x * 8 + w;
    float v = 0.f;
    if (i < n) {
        int start = g_rowstart[i];
        int deg = g_deg[i];
        float4 r4 = csr_gather4(g_sA, i, start, deg, grp, sub);
        float z = kv[c] * g_sdinv[i];
#pragma unroll
        for (int g = 0; g < 8; g++) {
            float vx = __shfl_sync(0xffffffffu, r4.x, g);
            float vy = __shfl_sync(0xffffffffu, r4.y, g);
            float vz = __shfl_sync(0xffffffffu, r4.z, g);
            float vw = __shfl_sync(0xffffffffu, r4.w, g);
            z += vx * Wsh[(4 * g + 0) * H + c] + vy * Wsh[(4 * g + 1) * H + c]
               + vz * Wsh[(4 * g + 2) * H + c] + vw * Wsh[(4 * g + 3) * H + c];
        }
        float di = g_dinv[i];
        v = fmaxf(z * di + bias[c], 0.f);
        g_sB[(size_t)i * H + c] = v * di;
    }
    sv[w][c] = v; sq[w][c] = v * v;
    __syncthreads();
    if (tid < H) {
        float s = 0.f, q = 0.f;
#pragma unroll
        for (int ww = 0; ww < 8; ww++) { s += sv[ww][tid]; q += sq[ww][tid]; }
        int b = blockIdx.x & (NBANK - 1);
        atomicAdd(&g_sumb[b][tid], (double)s);
        atomicAdd(&g_sumsqb[b][tid], (double)q);
    }
}

// conv3: grouped-float4 gather + matmul + bias/relu; rowsum + block max
__global__ void k_conv3(const float* __restrict__ bias, int n) {
    __shared__ float Wsh[H * H];
    __shared__ float kv[H];
    __shared__ unsigned bmax;
    int tid = threadIdx.x;
    for (int t = tid; t < H * H; t += 256) Wsh[t] = g_Wp[t];
    if (tid < H) kv[tid] = g_kvec[tid];
    if (tid == 0) bmax = 0u;
    __syncthreads();
    int c = tid & 31, w = tid >> 5;
    int grp = c >> 3, sub = c & 7;
    int i = blockIdx.x * 8 + w;
    if (i < n) {
        int start = g_rowstart[i];
        int deg = g_deg[i];
        float4 r4 = csr_gather4(g_sB, i, start, deg, grp, sub);
        float z = kv[c] * g_sdinv[i];
#pragma unroll
        for (int g = 0; g < 8; g++) {
            float vx = __shfl_sync(0xffffffffu, r4.x, g);
            float vy = __shfl_sync(0xffffffffu, r4.y, g);
            float vz = __shfl_sync(0xffffffffu, r4.z, g);
            float vw = __shfl_sync(0xffffffffu, r4.w, g);
            z += vx * Wsh[(4 * g + 0) * H + c] + vy * Wsh[(4 * g + 1) * H + c]
               + vz * Wsh[(4 * g + 2) * H + c] + vw * Wsh[(4 * g + 3) * H + c];
        }
        float v = fmaxf(z * g_dinv[i] + bias[c], 0.f);
        g_h[(size_t)i * H + c] = v;
        float rs = warp_sum(v);
        if (c == 0) {
            g_r[i] = rs;
            atomicMax(&bmax, __float_as_uint(rs));   // rs >= 0
        }
    }
    __syncthreads();
    if (tid == 0) atomicMax(&g_rmax_bits, bmax);
}

// merged heads stage 1: blocks [0,nbCount) do candidate counting,
// blocks [nbCount, nbCount+296) do softmax accumulation
__global__ void k_heads(const int* __restrict__ nt, int n, int nbCount) {
    if (blockIdx.x < (unsigned)nbCount) {
        int i = blockIdx.x * 256 + threadIdx.x;
        int flag = (i < n && nt[i] == 0);
        int cnt = __syncthreads_count(flag);
        if (threadIdx.x == 0) g_blockcnt[blockIdx.x] = cnt;
        return;
    }
    __shared__ double sw[H];
    __shared__ double se;
    int tid = threadIdx.x;
    int sb = blockIdx.x - nbCount;
    int nsb = 296;
    if (tid < H) sw[tid] = 0.0;
    if (tid == 0) se = 0.0;
    __syncthreads();
    int lane = tid & 31;
    int gw = sb * 8 + (tid >> 5);
    int nw = nsb * 8;
    float rmax = __uint_as_float(g_rmax_bits);
    double acc = 0.0, eacc = 0.0;
    for (int i = gw; i < n; i += nw) {
        float ev = expf(g_r[i] - rmax);
        acc += (double)(ev * g_h[(size_t)i * H + lane]);
        if (lane == 0) eacc += (double)ev;
    }
    atomicAdd(&sw[lane], acc);
    if (lane == 0) atomicAdd(&se, eacc);
    __syncthreads();
    if (tid < H) atomicAdd(&g_wsum[tid], sw[tid]);
    if (tid == 0) atomicAdd(&g_sumexp, se);
}

__global__ void k_scan_par(int nb) {
    __shared__ int sh[512];
    int tid = threadIdx.x;
    int v = (tid < nb) ? g_blockcnt[tid] : 0;
    sh[tid] = v;
    __syncthreads();
#pragma unroll
    for (int off = 1; off < 512; off <<= 1) {
        int t = (tid >= off) ? sh[tid - off] : 0;
        __syncthreads();
        sh[tid] += t;
        __syncthreads();
    }
    if (tid < nb) g_blockoff[tid] = sh[tid] - v;
    if (tid == nb - 1) g_C = sh[tid];
}

// merged: cand blocks [0,nbCount) (+ cleanup of deg/cursor),
// block nbCount runs dn head + zeroes run-state for next replay
__global__ void __launch_bounds__(256)
k_cand_dn(const int* __restrict__ nt,
          const float* __restrict__ Wc1, const float* __restrict__ bc1,
          const float* __restrict__ Wc2, const float* __restrict__ bc2,
          const float* __restrict__ Wd1, const float* __restrict__ bd1,
          const float* __restrict__ Wd2, const float* __restrict__ bd2,
          float* __restrict__ out, int n, int nbCount, int out_size) {
    int tid = threadIdx.x;
    if (blockIdx.x == (unsigned)nbCount) {
        // dn head (one warp) + state cleanup
        if (tid < 32) {
            int lane = tid;
            double se = g_sumexp;
            float gv = (float)(g_wsum[lane] / se);
            float acc = (lane < 16) ? bd1[lane] : 0.f;
#pragma unroll
            for (int k = 0; k < H; k++) {
                float gk = __shfl_sync(0xffffffffu, gv, k);
                acc += gk * ((lane < 16) ? Wd1[k * 16 + lane] : 0.f);
            }
            float z = fmaxf(acc, 0.f);
            float t = (lane < 16) ? z * Wd2[lane] : 0.f;
            t = warp_sum(t);
            if (lane == 0) {
                int C = g_C;
                if (C < out_size) out[C] = t + bd2[0];
            }
            __syncwarp();
            // cleanup AFTER reads
            g_wsum[lane] = 0.0;
            if (lane == 0) { g_sumexp = 0.0; g_rmax_bits = 0u; g_total = 0; }
        }
        return;
    }
    // cleanup for next run (deg/cursor unused after this point this run)
    int gi = blockIdx.x * 256 + tid;
    if (gi < n) { g_deg[gi] = 0; g_cursor[gi] = 0; }

    __shared__ float W1s[H * 16], b1s[16], W2s[16];
    __shared__ float b2s;
    __shared__ int warpsum[8], warpoff[8];
    for (int t = tid; t < H * 16; t += 256) W1s[t] = Wc1[t];
    if (tid < 16) { b1s[tid] = bc1[tid]; W2s[tid] = Wc2[tid]; }
    if (tid == 0) b2s = bc2[0];
    int i = gi;
    int flag = (i < n && nt[i] == 0);
    unsigned mask = __ballot_sync(0xffffffffu, flag);
    int lane = tid & 31, w = tid >> 5;
    if (lane == 0) warpsum[w] = __popc(mask);
    __syncthreads();
    if (tid == 0) {
        int run = 0;
#pragma unroll
        for (int ww = 0; ww < 8; ww++) { warpoff[ww] = run; run += warpsum[ww]; }
    }
    __syncthreads();
    if (!flag) return;
    int pos = g_blockoff[blockIdx.x] + warpoff[w] + __popc(mask & ((1u << lane) - 1));
    const float* hr = g_h + (size_t)i * H;
    float hreg[H];
#pragma unroll
    for (int k = 0; k < H; k++) hreg[k] = hr[k];
    float score = b2s;
#pragma unroll
    for (int j = 0; j < 16; j++) {
        float z = b1s[j];
#pragma unroll
        for (int k = 0; k < H; k++) z += hreg[k] * W1s[k * 16 + j];
        score += fmaxf(z, 0.f) * W2s[j];
    }
    int C = g_C;
    if (pos < out_size) out[pos] = score;
    int ip = C + 1 + pos;
    if (ip < out_size) out[ip] = (float)i;
}

// ---------------- host ----------------
extern "C" void kernel_launch(void* const* d_in, const int* in_sizes, int n_in,
                              void* d_out, int out_size) {
    const float* x   = (const float*)d_in[0];
    const int*   ei  = (const int*)d_in[1];
    const int*   nt  = (const int*)d_in[2];
    const float* W1  = (const float*)d_in[3];
    const float* b1  = (const float*)d_in[4];
    const float* W2  = (const float*)d_in[5];
    const float* b2  = (const float*)d_in[6];
    const float* W3  = (const float*)d_in[7];
    const float* b3  = (const float*)d_in[8];
    const float* g1  = (const float*)d_in[9];
    const float* be1 = (const float*)d_in[10];
    const float* g2  = (const float*)d_in[11];
    const float* be2 = (const float*)d_in[12];
    const float* Wc1 = (const float*)d_in[13];
    const float* bc1 = (const float*)d_in[14];
    const float* Wc2 = (const float*)d_in[15];
    const float* bc2 = (const float*)d_in[16];
    const float* Wd1 = (const float*)d_in[17];
    const float* bd1 = (const float*)d_in[18];
    const float* Wd2 = (const float*)d_in[19];
    const float* bd2 = (const float*)d_in[20];

    int n = in_sizes[0] / 3;
    int e = in_sizes[1] / 2;
    float* out = (float*)d_out;

    int nb256 = (n + 255) / 256;
    int eb256 = (e + 255) / 256;
    int mmb = (n + 7) / 8;
    double inv_n = 1.0 / (double)n;

    // CSR build (3 launches)
    k_prep<<<eb256, 256>>>(ei, e, n);
    k_build<<<nb256, 256>>>(x, n);
    k_bucket<<<eb256, 256>>>(ei, e, n);

    // convs (matmul commuted after gather; BN folded)
    k_conv1<<<mmb, 256>>>(W1, b1, n);
    k_bnparams<<<1, dim3(32, 32)>>>(W2, g1, be1, inv_n);
    k_conv2<<<mmb, 256>>>(b2, n);
    k_bnparams<<<1, dim3(32, 32)>>>(W3, g2, be2, inv_n);
    k_conv3<<<mmb, 256>>>(b3, n);

    // heads (3 launches)
    k_heads<<<nb256 + 296, 256>>>(nt, n, nb256);
    k_scan_par<<<1, 512>>>(nb256);
    k_cand_dn<<<nb256 + 1, 256>>>(nt, Wc1, bc1, Wc2, bc2,
                                  Wd1, bd1, Wd2, bd2, out, n, nb256, out_size);
}

// round 17
// speedup vs baseline: 1.0261x; 1.0261x over previous
#include <cuda_runtime.h>
#include <math.h>

#define NMAX 100000
#define EMAX 1600000
#define H 32
#define BN_EPS 1e-5f
#define NBANK 32
#define NBMAX ((NMAX + 255) / 256)

// ---------------- device scratch (zero-initialized at module load; every
// run restores the zero-invariant in its final kernel) ----------------
__device__ int      g_csr[EMAX];
__device__ int      g_rowstart[NMAX];
__device__ int      g_cursor[NMAX];              // must be 0 at entry
__device__ int      g_deg[NMAX];                 // must be 0 at entry
__device__ float    g_dinv[NMAX];
__device__ float    g_sdinv[NMAX];
__device__ __align__(16) float4 g_x4[NMAX];      // (x*dinv, dinv)
__device__ __align__(16) float g_sA[NMAX * H];
__device__ __align__(16) float g_sB[NMAX * H];
__device__ __align__(16) float g_h[NMAX * H];
__device__ float    g_r[NMAX];
__device__ double   g_sumb[NBANK][H], g_sumsqb[NBANK][H];  // zeroed by bnparams
__device__ float    g_Wp[H * H];
__device__ float    g_kvec[H];
__device__ unsigned g_rmax_bits;                 // must be 0 at entry
__device__ double   g_sumexp;                    // must be 0 at entry
__device__ double   g_wsum[H];                   // must be 0 at entry
__device__ int      g_total;                     // must be 0 at entry
__device__ int      g_blockcnt[NBMAX], g_blockoff[NBMAX], g_C;

__device__ __forceinline__ float warp_sum(float v) {
#pragma unroll
    for (int o = 16; o > 0; o >>= 1) v += __shfl_xor_sync(0xffffffffu, v, o);
    return v;
}

// grouped float4 gather: 4 neighbor-groups x 8 lanes
__device__ __forceinline__ float4 csr_gather4(const float* __restrict__ tab,
                                              int self, int start, int deg,
                                              int grp, int sub) {
    float4 r = make_float4(0.f, 0.f, 0.f, 0.f);
    for (int k = 0; k < deg; k += 8) {
        int k0 = k + grp, k1 = k + 4 + grp;
        if (k0 < deg) {
            int i0 = g_csr[start + k0];
            float4 a = ((const float4*)(tab + (size_t)i0 * H))[sub];
            r.x += a.x; r.y += a.y; r.z += a.z; r.w += a.w;
        }
        if (k1 < deg) {
            int i1 = g_csr[start + k1];
            float4 b = ((const float4*)(tab + (size_t)i1 * H))[sub];
            r.x += b.x; r.y += b.y; r.z += b.z; r.w += b.w;
        }
    }
#pragma unroll
    for (int o = 8; o < 32; o <<= 1) {
        r.x += __shfl_xor_sync(0xffffffffu, r.x, o);
        r.y += __shfl_xor_sync(0xffffffffu, r.y, o);
        r.z += __shfl_xor_sync(0xffffffffu, r.z, o);
        r.w += __shfl_xor_sync(0xffffffffu, r.w, o);
    }
    float4 s = ((const float4*)(tab + (size_t)self * H))[sub];
    r.x += s.x; r.y += s.y; r.z += s.z; r.w += s.w;
    return r;
}

// ---------------- kernels ----------------
// deg atomics (deg is 0 at entry by invariant)
__global__ void k_prep(const int* __restrict__ ei, int e, int n) {
    int t = blockIdx.x * blockDim.x + threadIdx.x;
    if (t >= e) return;
    int d = ei[e + t];
    if ((unsigned)d >= (unsigned)n) d = 0;
    atomicAdd(&g_deg[d], 1);
}

// dinv/x4 + rowstart via block-local scan + one atomicAdd
__global__ void k_build(const float* __restrict__ x, int n) {
    __shared__ int sh[256];
    __shared__ int base;
    int tid = threadIdx.x;
    int i = blockIdx.x * 256 + tid;
    int dv = (i < n) ? g_deg[i] : 0;
    if (i < n) {
        float di = rsqrtf((float)(dv + 1));
        g_dinv[i] = di;
        g_x4[i] = make_float4(x[(size_t)i * 3 + 0] * di,
                              x[(size_t)i * 3 + 1] * di,
                              x[(size_t)i * 3 + 2] * di, di);
    }
    sh[tid] = dv;
    __syncthreads();
#pragma unroll
    for (int off = 1; off < 256; off <<= 1) {
        int t = (tid >= off) ? sh[tid - off] : 0;
        __syncthreads();
        sh[tid] += t;
        __syncthreads();
    }
    if (tid == 255) base = atomicAdd(&g_total, sh[255]);
    __syncthreads();
    if (i < n) g_rowstart[i] = base + sh[tid] - dv;
}

__global__ void k_bucket(const int* __restrict__ ei, int e, int n) {
    int t = blockIdx.x * blockDim.x + threadIdx.x;
    if (t >= e) return;
    int s = ei[t];
    int d = ei[e + t];
    if ((unsigned)s >= (unsigned)n) s = 0;
    if ((unsigned)d >= (unsigned)n) d = 0;
    int pos = g_rowstart[d] + atomicAdd(&g_cursor[d], 1);
    g_csr[pos] = s;
}

// conv1: rank-3 gather (8 nbr-slots x 4 lanes, 1 float/lane) + W1 + banked stats
__global__ void k_conv1(const float* __restrict__ W, const float* __restrict__ bias,
                        int n) {
    __shared__ float Wsh[3 * H];
    __shared__ float sv[8][H], sq[8][H];
    int tid = threadIdx.x;
    for (int t = tid; t < 3 * H; t += 256) Wsh[t] = W[t];
    __syncthreads();
    int c = tid & 31, w = tid >> 5;
    int nb = c >> 2, comp = c & 3;   // 8 slots x 4 components
    int i = blockIdx.x * 8 + w;
    float v = 0.f;
    if (i < n) {
        int start = g_rowstart[i];
        int deg = g_deg[i];
        float r = 0.f;
        int k = nb;
        // unroll 2: two independent row loads in flight per iteration
        for (; k + 8 < deg; k += 16) {
            int i0 = g_csr[start + k];
            int i1 = g_csr[start + k + 8];
            float a = ((const float*)(g_x4 + i0))[comp];
            float b = ((const float*)(g_x4 + i1))[comp];
            r += a + b;
        }
        if (k < deg)
            r += ((const float*)(g_x4 + g_csr[start + k]))[comp];
        // reduce across the 8 slots (lanes with same comp)
#pragma unroll
        for (int o = 4; o < 32; o <<= 1)
            r += __shfl_xor_sync(0xffffffffu, r, o);
        r += ((const float*)(g_x4 + i))[comp];   // self row, per-component
        float ax = __shfl_sync(0xffffffffu, r, 0);
        float ay = __shfl_sync(0xffffffffu, r, 1);
        float az = __shfl_sync(0xffffffffu, r, 2);
        float aw = __shfl_sync(0xffffffffu, r, 3);
        if (c == 0) g_sdinv[i] = aw;
        float di = g_dinv[i];
        float z = ax * Wsh[0 * H + c] + ay * Wsh[1 * H + c] + az * Wsh[2 * H + c];
        v = fmaxf(z * di + bias[c], 0.f);
        g_sA[(size_t)i * H + c] = v * di;
    }
    sv[w][c] = v; sq[w][c] = v * v;
    __syncthreads();
    if (tid < H) {
        float s = 0.f, q = 0.f;
#pragma unroll
        for (int ww = 0; ww < 8; ww++) { s += sv[ww][tid]; q += sq[ww][tid]; }
        int b = blockIdx.x & (NBANK - 1);
        atomicAdd(&g_sumb[b][tid], (double)s);
        atomicAdd(&g_sumsqb[b][tid], (double)q);
    }
}

// BN params folded into next layer's weight (reads banked stats, zeroes them)
__global__ void k_bnparams(const float* __restrict__ W, const float* __restrict__ g,
                           const float* __restrict__ be, double inv_n) {
    __shared__ float sscale[H], sshift[H];
    int k = threadIdx.x, j = threadIdx.y;
    if (j == 0) {
        double s = 0.0, q = 0.0;
        for (int b = 0; b < NBANK; b++) { s += g_sumb[b][k]; q += g_sumsqb[b][k]; }
        double mu = s * inv_n;
        double var = q * inv_n - mu * mu;
        float scale = g[k] * rsqrtf((float)var + BN_EPS);
        sscale[k] = scale;
        sshift[k] = be[k] - (float)mu * scale;
    }
    __syncthreads();
    float wv = W[k * H + j];
    g_Wp[k * H + j] = sscale[k] * wv;
    float t = sshift[k] * wv;
#pragma unroll
    for (int o = 16; o > 0; o >>= 1) t += __shfl_xor_sync(0xffffffffu, t, o);
    if (k == 0) g_kvec[j] = t;
    g_sumb[j][k] = 0.0;
    g_sumsqb[j][k] = 0.0;
}

// conv2: grouped-float4 gather + commuted matmul + bias/relu + banked stats
__global__ void k_conv2(const float* __restrict__ bias, int n) {
    __shared__ float Wsh[H * H];
    __shared__ float kv[H];
    __shared__ float sv[8][H], sq[8][H];
    int tid = threadIdx.x;
    for (int t = tid; t < H * H; t += 256) Wsh[t] = g_Wp[t];
    if (tid < H) kv[tid] = g_kvec[tid];
    __syncthreads();
    int c = tid & 31, w = tid >> 5;
    int grp = c >> 3, sub = c & 7;
    int i = blockIdx.x * 8 + w;
    float v = 0.f;
    if (i < n) {
        int start = g_rowstart[i];
        int deg = g_deg[i];
        float4 r4 = csr_gather4(g_sA, i, start, deg, grp, sub);
        float z = kv[c] * g_sdinv[i];
#pragma unroll
        for (int g = 0; g < 8; g++) {
            float vx = __shfl_sync(0xffffffffu, r4.x, g);
            float vy = __shfl_sync(0xffffffffu, r4.y, g);
            float vz = __shfl_sync(0xffffffffu, r4.z, g);
            float vw = __shfl_sync(0xffffffffu, r4.w, g);
            z += vx * Wsh[(4 * g + 0) * H + c] + vy * Wsh[(4 * g + 1) * H + c]
               + vz * Wsh[(4 * g + 2) * H + c] + vw * Wsh[(4 * g + 3) * H + c];
        }
        float di = g_dinv[i];
        v = fmaxf(z * di + bias[c], 0.f);
        g_sB[(size_t)i * H + c] = v * di;
    }
    sv[w][c] = v; sq[w][c] = v * v;
    __syncthreads();
    if (tid < H) {
        float s = 0.f, q = 0.f;
#pragma unroll
        for (int ww = 0; ww < 8; ww++) { s += sv[ww][tid]; q += sq[ww][tid]; }
        int b = blockIdx.x & (NBANK - 1);
        atomicAdd(&g_sumb[b][tid], (double)s);
        atomicAdd(&g_sumsqb[b][tid], (double)q);
    }
}

// conv3: grouped-float4 gather + matmul + bias/relu; rowsum + block max
__global__ void k_conv3(const float* __restrict__ bias, int n) {
    __shared__ float Wsh[H * H];
    __shared__ float kv[H];
    __shared__ unsigned bmax;
    int tid = threadIdx.x;
    for (int t = tid; t < H * H; t += 256) Wsh[t] = g_Wp[t];
    if (tid < H) kv[tid] = g_kvec[tid];
    if (tid == 0) bmax = 0u;
    __syncthreads();
    int c = tid & 31, w = tid >> 5;
    int grp = c >> 3, sub = c & 7;
    int i = blockIdx.x * 8 + w;
    if (i < n) {
        int start = g_rowstart[i];
        int deg = g_deg[i];
        float4 r4 = csr_gather4(g_sB, i, start, deg, grp, sub);
        float z = kv[c] * g_sdinv[i];
#pragma unroll
        for (int g = 0; g < 8; g++) {
            float vx = __shfl_sync(0xffffffffu, r4.x, g);
            float vy = __shfl_sync(0xffffffffu, r4.y, g);
            float vz = __shfl_sync(0xffffffffu, r4.z, g);
            float vw = __shfl_sync(0xffffffffu, r4.w, g);
            z += vx * Wsh[(4 * g + 0) * H + c] + vy * Wsh[(4 * g + 1) * H + c]
               + vz * Wsh[(4 * g + 2) * H + c] + vw * Wsh[(4 * g + 3) * H + c];
        }
        float v = fmaxf(z * g_dinv[i] + bias[c], 0.f);
        g_h[(size_t)i * H + c] = v;
        float rs = warp_sum(v);
        if (c == 0) {
            g_r[i] = rs;
            atomicMax(&bmax, __float_as_uint(rs));   // rs >= 0
        }
    }
    __syncthreads();
    if (tid == 0) atomicMax(&g_rmax_bits, bmax);
}

// merged heads stage 1: blocks [0,nbCount) candidate counting,
// blocks [nbCount, nbCount+296) softmax accumulation
__global__ void k_heads(const int* __restrict__ nt, int n, int nbCount) {
    if (blockIdx.x < (unsigned)nbCount) {
        int i = blockIdx.x * 256 + threadIdx.x;
        int flag = (i < n && nt[i] == 0);
        int cnt = __syncthreads_count(flag);
        if (threadIdx.x == 0) g_blockcnt[blockIdx.x] = cnt;
        return;
    }
    __shared__ double sw[H];
    __shared__ double se;
    int tid = threadIdx.x;
    int sb = blockIdx.x - nbCount;
    int nsb = 296;
    if (tid < H) sw[tid] = 0.0;
    if (tid == 0) se = 0.0;
    __syncthreads();
    int lane = tid & 31;
    int gw = sb * 8 + (tid >> 5);
    int nw = nsb * 8;
    float rmax = __uint_as_float(g_rmax_bits);
    double acc = 0.0, eacc = 0.0;
    for (int i = gw; i < n; i += nw) {
        float ev = expf(g_r[i] - rmax);
        acc += (double)(ev * g_h[(size_t)i * H + lane]);
        if (lane == 0) eacc += (double)ev;
    }
    atomicAdd(&sw[lane], acc);
    if (lane == 0) atomicAdd(&se, eacc);
    __syncthreads();
    if (tid < H) atomicAdd(&g_wsum[tid], sw[tid]);
    if (tid == 0) atomicAdd(&g_sumexp, se);
}

__global__ void k_scan_par(int nb) {
    __shared__ int sh[512];
    int tid = threadIdx.x;
    int v = (tid < nb) ? g_blockcnt[tid] : 0;
    sh[tid] = v;
    __syncthreads();
#pragma unroll
    for (int off = 1; off < 512; off <<= 1) {
        int t = (tid >= off) ? sh[tid - off] : 0;
        __syncthreads();
        sh[tid] += t;
        __syncthreads();
    }
    if (tid < nb) g_blockoff[tid] = sh[tid] - v;
    if (tid == nb - 1) g_C = sh[tid];
}

// merged: cand blocks [0,nbCount) (+ cleanup), block nbCount = dn head + state reset
__global__ void __launch_bounds__(256)
k_cand_dn(const int* __restrict__ nt,
          const float* __restrict__ Wc1, const float* __restrict__ bc1,
          const float* __restrict__ Wc2, const float* __restrict__ bc2,
          const float* __restrict__ Wd1, const float* __restrict__ bd1,
          const float* __restrict__ Wd2, const float* __restrict__ bd2,
          float* __restrict__ out, int n, int nbCount, int out_size) {
    int tid = threadIdx.x;
    if (blockIdx.x == (unsigned)nbCount) {
        if (tid < 32) {
            int lane = tid;
            double se = g_sumexp;
            float gv = (float)(g_wsum[lane] / se);
            float acc = (lane < 16) ? bd1[lane] : 0.f;
#pragma unroll
            for (int k = 0; k < H; k++) {
                float gk = __shfl_sync(0xffffffffu, gv, k);
                acc += gk * ((lane < 16) ? Wd1[k * 16 + lane] : 0.f);
            }
            float z = fmaxf(acc, 0.f);
            float t = (lane < 16) ? z * Wd2[lane] : 0.f;
            t = warp_sum(t);
            if (lane == 0) {
                int C = g_C;
                if (C < out_size) out[C] = t + bd2[0];
            }
            __syncwarp();
            g_wsum[lane] = 0.0;
            if (lane == 0) { g_sumexp = 0.0; g_rmax_bits = 0u; g_total = 0; }
        }
        return;
    }
    int gi = blockIdx.x * 256 + tid;
    if (gi < n) { g_deg[gi] = 0; g_cursor[gi] = 0; }

    __shared__ float W1s[H * 16], b1s[16], W2s[16];
    __shared__ float b2s;
    __shared__ int warpsum[8], warpoff[8];
    for (int t = tid; t < H * 16; t += 256) W1s[t] = Wc1[t];
    if (tid < 16) { b1s[tid] = bc1[tid]; W2s[tid] = Wc2[tid]; }
    if (tid == 0) b2s = bc2[0];
    int i = gi;
    int flag = (i < n && nt[i] == 0);
    unsigned mask = __ballot_sync(0xffffffffu, flag);
    int lane = tid & 31, w = tid >> 5;
    if (lane == 0) warpsum[w] = __popc(mask);
    __syncthreads();
    if (tid == 0) {
        int run = 0;
#pragma unroll
        for (int ww = 0; ww < 8; ww++) { warpoff[ww] = run; run += warpsum[ww]; }
    }
    __syncthreads();
    if (!flag) return;
    int pos = g_blockoff[blockIdx.x] + warpoff[w] + __popc(mask & ((1u << lane) - 1));
    const float* hr = g_h + (size_t)i * H;
    float hreg[H];
#pragma unroll
    for (int k = 0; k < H; k++) hreg[k] = hr[k];
    float score = b2s;
#pragma unroll
    for (int j = 0; j < 16; j++) {
        float z = b1s[j];
#pragma unroll
        for (int k = 0; k < H; k++) z += hreg[k] * W1s[k * 16 + j];
        score += fmaxf(z, 0.f) * W2s[j];
    }
    int C = g_C;
    if (pos < out_size) out[pos] = score;
    int ip = C + 1 + pos;
    if (ip < out_size) out[ip] = (float)i;
}

// ---------------- host ----------------
extern "C" void kernel_launch(void* const* d_in, const int* in_sizes, int n_in,
                              void* d_out, int out_size) {
    const float* x   = (const float*)d_in[0];
    const int*   ei  = (const int*)d_in[1];
    const int*   nt  = (const int*)d_in[2];
    const float* W1  = (const float*)d_in[3];
    const float* b1  = (const float*)d_in[4];
    const float* W2  = (const float*)d_in[5];
    const float* b2  = (const float*)d_in[6];
    const float* W3  = (const float*)d_in[7];
    const float* b3  = (const float*)d_in[8];
    const float* g1  = (const float*)d_in[9];
    const float* be1 = (const float*)d_in[10];
    const float* g2  = (const float*)d_in[11];
    const float* be2 = (const float*)d_in[12];
    const float* Wc1 = (const float*)d_in[13];
    const float* bc1 = (const float*)d_in[14];
    const float* Wc2 = (const float*)d_in[15];
    const float* bc2 = (const float*)d_in[16];
    const float* Wd1 = (const float*)d_in[17];
    const float* bd1 = (const float*)d_in[18];
    const float* Wd2 = (const float*)d_in[19];
    const float* bd2 = (const float*)d_in[20];

    int n = in_sizes[0] / 3;
    int e = in_sizes[1] / 2;
    float* out = (float*)d_out;

    int nb256 = (n + 255) / 256;
    int eb256 = (e + 255) / 256;
    int mmb = (n + 7) / 8;
    double inv_n = 1.0 / (double)n;

    // CSR build
    k_prep<<<eb256, 256>>>(ei, e, n);
    k_build<<<nb256, 256>>>(x, n);
    k_bucket<<<eb256, 256>>>(ei, e, n);

    // convs (matmul commuted after gather; BN folded)
    k_conv1<<<mmb, 256>>>(W1, b1, n);
    k_bnparams<<<1, dim3(32, 32)>>>(W2, g1, be1, inv_n);
    k_conv2<<<mmb, 256>>>(b2, n);
    k_bnparams<<<1, dim3(32, 32)>>>(W3, g2, be2, inv_n);
    k_conv3<<<mmb, 256>>>(b3, n);

    // heads
    k_heads<<<nb256 + 296, 256>>>(nt, n, nb256);
    k_scan_par<<<1, 512>>>(nb256);
    k_cand_dn<<<nb256 + 1, 256>>>(nt, Wc1, bc1, Wc2, bc2,
                                  Wd1, bd1, Wd2, bd2, out, n, nb256, out_size);
}